// round 13
// baseline (speedup 1.0000x reference)
#include <cuda_runtime.h>
#include <math_constants.h>

#define B 64
#define T 2048
#define EMB 512
#define ATT 128
#define NF 32
#define KW 31
#define PADW 15
#define TB 64
#define NSEG (T / TB)          // 32
#define NTASK (NSEG * B)       // 2048
#define NBLK 740               // 148 SMs x 5 resident blocks

__device__ float g_q[B * ATT];
__device__ float g_sum[B];
__device__ float g_wlocT[NF * ATT];
__device__ float4 g_ctxp[NSEG * B * (EMB / 4)];   // per-seg ctx partials

typedef unsigned long long u64;
typedef unsigned int u32;

__device__ __forceinline__ u64 pack2(float lo, float hi) {
    u64 r; asm("mov.b64 %0, {%1, %2};" : "=l"(r) : "f"(lo), "f"(hi)); return r;
}
__device__ __forceinline__ void unpack2(u64 v, float& lo, float& hi) {
    asm("mov.b64 {%0, %1}, %2;" : "=f"(lo), "=f"(hi) : "l"(v));
}
__device__ __forceinline__ u64 add2(u64 a, u64 b) {
    u64 r; asm("add.rn.f32x2 %0, %1, %2;" : "=l"(r) : "l"(a), "l"(b)); return r;
}
__device__ __forceinline__ void fma2(u64& d, u64 a, u64 b) {
    asm("fma.rn.f32x2 %0, %1, %2, %0;" : "+l"(d) : "l"(a), "l"(b));
}
__device__ __forceinline__ float tanh_apx(float x) {
    float r; asm("tanh.approx.f32 %0, %1;" : "=f"(r) : "f"(x)); return r;
}

// ---------------------------------------------------------------------------
// Kernel 1: q = hidden @ W_dec^T. grid (B, 16), 256 thr, one row per warp.
// PDL primary: signals dependents immediately.
// ---------------------------------------------------------------------------
__global__ void __launch_bounds__(256)
prep_kernel(const float* __restrict__ HID,
            const float* __restrict__ WDEC,
            const float* __restrict__ WLOC) {
    asm volatile("griddepcontrol.launch_dependents;");

    const int b = blockIdx.x;
    const int chunk = blockIdx.y;
    const int tid = threadIdx.x;
    const int w = tid >> 5, lane = tid & 31;

    if (chunk == 0 && tid == 0) g_sum[b] = 0.f;
    if (b == 0 && chunk == 1) {
        for (int idx = tid; idx < NF * ATT; idx += 256) {
            int a = idx >> 5, c = idx & 31;
            g_wlocT[c * ATT + a] = WLOC[idx];
        }
    }

    const int a = chunk * 8 + w;
    const float4* __restrict__ H4 = (const float4*)(HID + b * 1024);
    const float4* __restrict__ WD4 = (const float4*)WDEC + a * 256;

    float acc = 0.f;
    #pragma unroll
    for (int j = 0; j < 8; j++) {
        float4 h = H4[j * 32 + lane];
        float4 v = WD4[j * 32 + lane];
        acc += h.x * v.x + h.y * v.y + h.z * v.z + h.w * v.w;
    }
    #pragma unroll
    for (int s = 16; s; s >>= 1)
        acc += __shfl_xor_sync(0xffffffffu, acc, s);
    if (lane == 0) g_q[b * ATT + a] = acc;
}

// ---------------------------------------------------------------------------
// Kernel 2 (FUSED, PERSISTENT): one wave of NBLK blocks; each block strides
// over (seg,b) tasks. W_loc / conv-weight smem loaded once per block.
// Per task: cum load -> conv -> stage2 (weights) -> context partial.
// ---------------------------------------------------------------------------
__global__ void __launch_bounds__(128)
fused_kernel(const float* __restrict__ MEM,
             const float* __restrict__ MA,
             const float* __restrict__ CUM,
             const int* __restrict__ MASK,
             const float* __restrict__ WCONV,
             const float* __restrict__ WE,
             float* __restrict__ WOUT) {
    __shared__ float s_wloc[NF][ATT];                 // 16KB (persistent)
    __shared__ union {                                // 17KB overlay (per task)
        u64    locd[NF][TB + 2];
        float4 ctx[4 * 128];
    } ov;
    __shared__ alignas(16) float2 s_cum2[TB + 2 * PADW + 2];
    __shared__ float s_wcraw[NF * 2 * KW];            // 7.75KB (persistent)
    __shared__ float s_w[TB];

    const int tid = threadIdx.x;
    const int w = tid >> 5, lane = tid & 31;
    const int tl = w * 16;

    // persistent setup (independent of prep)
    for (int i = tid; i < NF * 2 * KW; i += 128) s_wcraw[i] = WCONV[i];

    const float4 we4 = ((const float4*)WE)[lane];
    const float4* __restrict__ MA4 = (const float4*)MA;
    bool first = true;

    for (int task = blockIdx.x; task < NTASK; task += NBLK) {
        const int b = task >> 5;          // 0..63
        const int seg = task & 31;        // 0..31
        const int t0 = seg * TB;

        // ---- cum halo tile for this task ----
        for (int j = tid; j < TB + 2 * PADW + 2; j += 128) {
            int tg = t0 + j - PADW;
            float a0 = 0.f, a1 = 0.f;
            if (tg >= 0 && tg < T) {
                a0 = CUM[(b * 2 + 0) * T + tg];
                a1 = CUM[(b * 2 + 1) * T + tg];
            }
            s_cum2[j] = make_float2(a0, a1);
        }
        __syncthreads();

        // ---- stage 1: conv1d, lane = channel, t in pairs ----
        {
            u64 wk[KW];
            #pragma unroll
            for (int k = 0; k < KW; k++)
                wk[k] = pack2(s_wcraw[(lane * 2 + 0) * KW + k],
                              s_wcraw[(lane * 2 + 1) * KW + k]);
            #pragma unroll 2
            for (int u = 0; u < 8; u++) {
                const int tp = tl + 2 * u;
                u64 a0 = 0ull, a1 = 0ull;
                #pragma unroll
                for (int m = 0; m < 16; m++) {
                    float4 F = *(const float4*)&s_cum2[tp + 2 * m];
                    u64 flo = pack2(F.x, F.y);
                    u64 fhi = pack2(F.z, F.w);
                    fma2(a0, wk[2 * m], flo);
                    if (2 * m + 1 < KW) fma2(a0, wk[2 * m + 1], fhi);
                    if (m > 0) fma2(a1, wk[2 * m - 1], flo);
                    fma2(a1, wk[2 * m], fhi);
                }
                float l0, h0, l1, h1;
                unpack2(a0, l0, h0);
                unpack2(a1, l1, h1);
                float v0 = l0 + h0, v1 = l1 + h1;
                ov.locd[lane][tp]     = pack2(v0, v0);
                ov.locd[lane][tp + 1] = pack2(v1, v1);
            }
        }

        if (first) {
            // wait for prep once per block; fill persistent W_loc tile
            asm volatile("griddepcontrol.wait;" ::: "memory");
            const float4* __restrict__ src = (const float4*)g_wlocT;
            float4* dst = (float4*)s_wloc;
            #pragma unroll
            for (int j = 0; j < 8; j++) dst[tid + j * 128] = src[tid + j * 128];
            first = false;
        }
        __syncthreads();

        // ---- stage 2: two passes of 8 t, register-blocked ----
        const float4 q4 = *((const float4*)(g_q + b * ATT) + lane);
        const u64 q01 = pack2(q4.x, q4.y);
        const u64 q23 = pack2(q4.z, q4.w);

        int mv = 0;
        if (lane < 16) mv = MASK[b * T + t0 + tl + lane];
        const unsigned mk16 = __ballot_sync(0xffffffffu, mv != 0) & 0xffffu;

        float psum = 0.f;
        #pragma unroll
        for (int p = 0; p < 2; p++) {
            const int ts = tl + p * 8;
            const unsigned mb = (mk16 >> (p * 8)) & 0xffu;

            u64 v01[8], v23[8];
            #pragma unroll
            for (int j = 0; j < 8; j++) {
                if (!((mb >> j) & 1u)) {
                    const int t = t0 + ts + j;
                    float4 m = MA4[((size_t)b * T + t) * (ATT / 4) + lane];
                    v01[j] = add2(q01, pack2(m.x, m.y));
                    v23[j] = add2(q23, pack2(m.z, m.w));
                } else {
                    v01[j] = q01; v23[j] = q23;
                }
            }
            #pragma unroll 4
            for (int c = 0; c < NF; c++) {
                float4 wf = ((const float4*)s_wloc[c])[lane];   // LDS.128
                u64 w01 = pack2(wf.x, wf.y);
                u64 w23 = pack2(wf.z, wf.w);
                #pragma unroll
                for (int r = 0; r < 4; r++) {
                    ulonglong2 L = *(const ulonglong2*)&ov.locd[c][ts + 2 * r];
                    fma2(v01[2 * r],     L.x, w01);
                    fma2(v23[2 * r],     L.x, w23);
                    fma2(v01[2 * r + 1], L.y, w01);
                    fma2(v23[2 * r + 1], L.y, w23);
                }
            }

            float myw = 0.f;
            #pragma unroll
            for (int j = 0; j < 8; j++) {
                if (!((mb >> j) & 1u)) {
                    float a0, a1, a2, a3;
                    unpack2(v01[j], a0, a1);
                    unpack2(v23[j], a2, a3);
                    float e = we4.x * tanh_apx(a0) + we4.y * tanh_apx(a1)
                            + we4.z * tanh_apx(a2) + we4.w * tanh_apx(a3);
                    #pragma unroll
                    for (int sh = 16; sh; sh >>= 1)
                        e += __shfl_xor_sync(0xffffffffu, e, sh);
                    float wexp = __expf(e);   // |e| small: no max subtraction
                    if (lane == j) myw = wexp;
                    psum += wexp;
                }
            }
            if (lane < 8) {
                WOUT[b * T + t0 + ts + lane] = myw;  // unnormalized; masked -> 0
                s_w[ts + lane] = myw;
            }
        }
        if (lane == 0) atomicAdd(&g_sum[b], psum);

        __syncthreads();   // s_w ready; locd reads done (overlay safe)

        // ---- fused context accumulation: warp covers its own 16 t rows ----
        const float4* __restrict__ M4 =
            (const float4*)MEM + ((size_t)b * T + t0) * (EMB / 4);
        float4 acc0 = make_float4(0.f, 0.f, 0.f, 0.f);
        float4 acc1 = acc0, acc2 = acc0, acc3 = acc0;
        #pragma unroll 4
        for (int j = 0; j < 16; j++) {
            float wt = s_w[tl + j];
            if (wt != 0.f) {   // warp-uniform skip of masked rows
                const float4* row = M4 + (size_t)(tl + j) * (EMB / 4);
                float4 m0 = __ldcs(row + 0 * 32 + lane);
                float4 m1 = __ldcs(row + 1 * 32 + lane);
                float4 m2 = __ldcs(row + 2 * 32 + lane);
                float4 m3 = __ldcs(row + 3 * 32 + lane);
                acc0.x += wt * m0.x; acc0.y += wt * m0.y; acc0.z += wt * m0.z; acc0.w += wt * m0.w;
                acc1.x += wt * m1.x; acc1.y += wt * m1.y; acc1.z += wt * m1.z; acc1.w += wt * m1.w;
                acc2.x += wt * m2.x; acc2.y += wt * m2.y; acc2.z += wt * m2.z; acc2.w += wt * m2.w;
                acc3.x += wt * m3.x; acc3.y += wt * m3.y; acc3.z += wt * m3.z; acc3.w += wt * m3.w;
            }
        }
        ov.ctx[w * 128 + 0 * 32 + lane] = acc0;
        ov.ctx[w * 128 + 1 * 32 + lane] = acc1;
        ov.ctx[w * 128 + 2 * 32 + lane] = acc2;
        ov.ctx[w * 128 + 3 * 32 + lane] = acc3;
        __syncthreads();

        // cross-warp reduce + store per-segment partial (coalesced)
        float4 r0 = ov.ctx[tid];
        float4 r1 = ov.ctx[128 + tid];
        float4 r2 = ov.ctx[256 + tid];
        float4 r3 = ov.ctx[384 + tid];
        float4 r = make_float4(r0.x + r1.x + r2.x + r3.x,
                               r0.y + r1.y + r2.y + r3.y,
                               r0.z + r1.z + r2.z + r3.z,
                               r0.w + r1.w + r2.w + r3.w);
        g_ctxp[(seg * B + b) * 128 + tid] = r;
        __syncthreads();   // ctx overlay reads done before next task's conv
    }
}

// ---------------------------------------------------------------------------
// Kernel 3: normalize weights + reduce ctx partials. grid (B), 256 thr.
// ---------------------------------------------------------------------------
__global__ void __launch_bounds__(256)
normalize_kernel(float* __restrict__ WROW, float* __restrict__ CTX) {
    const int b = blockIdx.x;
    const int tid = threadIdx.x;
    const float inv = 1.f / g_sum[b];

    float4* __restrict__ W4 = (float4*)(WROW + b * T);
    #pragma unroll
    for (int j = 0; j < 2; j++) {
        float4 v = W4[tid + j * 256];
        v.x *= inv; v.y *= inv; v.z *= inv; v.w *= inv;
        W4[tid + j * 256] = v;
    }
    if (tid < 128) {
        float4 r = make_float4(0.f, 0.f, 0.f, 0.f);
        #pragma unroll
        for (int seg = 0; seg < NSEG; seg++) {
            float4 p = g_ctxp[(seg * B + b) * 128 + tid];
            r.x += p.x; r.y += p.y; r.z += p.z; r.w += p.w;
        }
        ((float4*)CTX)[b * 128 + tid] =
            make_float4(r.x * inv, r.y * inv, r.z * inv, r.w * inv);
    }
}

// ---------------------------------------------------------------------------
extern "C" void kernel_launch(void* const* d_in, const int* in_sizes, int n_in,
                              void* d_out, int out_size) {
    const float* hid   = (const float*)d_in[0];
    const float* mem   = (const float*)d_in[1];
    const float* ma    = (const float*)d_in[2];
    const float* cum   = (const float*)d_in[3];
    const int*   mask  = (const int*)d_in[4];
    const float* wdec  = (const float*)d_in[5];
    const float* wconv = (const float*)d_in[6];
    const float* wloc  = (const float*)d_in[7];
    const float* we    = (const float*)d_in[8];

    float* out_ctx = (float*)d_out;
    float* out_w   = (float*)d_out + B * EMB;

    dim3 gp(B, 16);
    prep_kernel<<<gp, 256>>>(hid, wdec, wloc);

    cudaLaunchConfig_t cfg = {};
    cfg.gridDim = dim3(NBLK);
    cfg.blockDim = dim3(128);
    cfg.dynamicSmemBytes = 0;
    cfg.stream = 0;
    cudaLaunchAttribute attrs[1];
    attrs[0].id = cudaLaunchAttributeProgrammaticStreamSerialization;
    attrs[0].val.programmaticStreamSerializationAllowed = 1;
    cfg.attrs = attrs;
    cfg.numAttrs = 1;
    cudaLaunchKernelEx(&cfg, fused_kernel, mem, ma, cum, mask, wconv, we, out_w);

    normalize_kernel<<<B, 256>>>(out_w, out_ctx);
}

// round 14
// speedup vs baseline: 1.2865x; 1.2865x over previous
#include <cuda_runtime.h>
#include <math_constants.h>

#define B 64
#define T 2048
#define EMB 512
#define ATT 128
#define NF 32
#define KW 31
#define PADW 15
#define TB 64
#define NSEG (T / TB)   // 32

__device__ float g_q[B * ATT];
__device__ float g_sum[B];
__device__ float g_wlocT[NF * ATT];
__device__ float2 g_wconv2[KW * NF];              // (W[c,0,k], W[c,1,k]) at [k*NF+c]
__device__ float4 g_ctxp[NSEG * B * (EMB / 4)];   // per-seg ctx partials

typedef unsigned long long u64;
typedef unsigned int u32;

__device__ __forceinline__ u64 pack2(float lo, float hi) {
    u64 r; asm("mov.b64 %0, {%1, %2};" : "=l"(r) : "f"(lo), "f"(hi)); return r;
}
__device__ __forceinline__ void unpack2(u64 v, float& lo, float& hi) {
    asm("mov.b64 {%0, %1}, %2;" : "=f"(lo), "=f"(hi) : "l"(v));
}
__device__ __forceinline__ u64 add2(u64 a, u64 b) {
    u64 r; asm("add.rn.f32x2 %0, %1, %2;" : "=l"(r) : "l"(a), "l"(b)); return r;
}
__device__ __forceinline__ void fma2(u64& d, u64 a, u64 b) {
    asm("fma.rn.f32x2 %0, %1, %2, %0;" : "+l"(d) : "l"(a), "l"(b));
}
__device__ __forceinline__ float tanh_apx(float x) {
    float r; asm("tanh.approx.f32 %0, %1;" : "=f"(r) : "f"(x)); return r;
}

// ---------------------------------------------------------------------------
// Kernel 1: q = hidden @ W_dec^T. grid (B, 16), 256 thr, one row per warp.
// PDL primary: signals dependents immediately. Also pre-transposes weights.
// ---------------------------------------------------------------------------
__global__ void __launch_bounds__(256)
prep_kernel(const float* __restrict__ HID,
            const float* __restrict__ WDEC,
            const float* __restrict__ WLOC,
            const float* __restrict__ WCONV) {
    asm volatile("griddepcontrol.launch_dependents;");

    const int b = blockIdx.x;
    const int chunk = blockIdx.y;
    const int tid = threadIdx.x;
    const int w = tid >> 5, lane = tid & 31;

    if (chunk == 0 && tid == 0) g_sum[b] = 0.f;
    if (b == 0 && chunk == 1) {
        for (int idx = tid; idx < NF * ATT; idx += 256) {
            int a = idx >> 5, c = idx & 31;
            g_wlocT[c * ATT + a] = WLOC[idx];
        }
        for (int idx = tid; idx < KW * NF; idx += 256) {
            int c = idx & 31, k = idx >> 5;
            g_wconv2[k * NF + c] = make_float2(WCONV[(c * 2 + 0) * KW + k],
                                               WCONV[(c * 2 + 1) * KW + k]);
        }
    }

    const int a = chunk * 8 + w;
    const float4* __restrict__ H4 = (const float4*)(HID + b * 1024);
    const float4* __restrict__ WD4 = (const float4*)WDEC + a * 256;

    float acc = 0.f;
    #pragma unroll
    for (int j = 0; j < 8; j++) {
        float4 h = H4[j * 32 + lane];
        float4 v = WD4[j * 32 + lane];
        acc += h.x * v.x + h.y * v.y + h.z * v.z + h.w * v.w;
    }
    #pragma unroll
    for (int s = 16; s; s >>= 1)
        acc += __shfl_xor_sync(0xffffffffu, acc, s);
    if (lane == 0) g_q[b * ATT + a] = acc;
}

// ---------------------------------------------------------------------------
// Kernel 2 (FUSED): unnormalized weights w'[b,t] AND per-segment context
// partial. grid (NSEG, B), block 128; warp owns 16 t.
// Conv weights via __ldg from g_wconv2 (no smem buffer) -> 34KB smem,
// 6 blocks/SM instead of 5.
// ---------------------------------------------------------------------------
__global__ void __launch_bounds__(128)
fused_kernel(const float* __restrict__ MEM,
             const float* __restrict__ MA,
             const float* __restrict__ CUM,
             const int* __restrict__ MASK,
             const float* __restrict__ WE,
             float* __restrict__ WOUT) {
    __shared__ float s_wloc[NF][ATT];                 // 16KB
    __shared__ union {                                // 16.9KB (overlay)
        u64    locd[NF][TB + 2];
        float4 ctx[4 * 128];                          // used after stage 2
    } ov;
    __shared__ alignas(16) float2 s_cum2[TB + 2 * PADW + 2];
    __shared__ float s_w[TB];

    const int seg = blockIdx.x;
    const int b = blockIdx.y;
    const int t0 = seg * TB;
    const int tid = threadIdx.x;
    const int w = tid >> 5, lane = tid & 31;
    const int tl = w * 16;

    // ---- pre-wait phase (independent of prep's q; g_wconv2 comes from prep,
    // but conv consumes it AFTER the wait would... note: g_wconv2 is written
    // by prep, so conv weights must be read post-wait. Keep cum load pre-wait.
    for (int j = tid; j < TB + 2 * PADW + 2; j += 128) {
        int tg = t0 + j - PADW;
        float a0 = 0.f, a1 = 0.f;
        if (tg >= 0 && tg < T) {
            a0 = CUM[(b * 2 + 0) * T + tg];
            a1 = CUM[(b * 2 + 1) * T + tg];
        }
        s_cum2[j] = make_float2(a0, a1);
    }
    __syncthreads();

    // ---- wait for prep (g_q, g_wlocT, g_wconv2 visible) ----
    asm volatile("griddepcontrol.wait;" ::: "memory");

    // stage 1: conv1d, lane = channel, t in pairs (16B broadcasts)
    {
        u64 wk[KW];
        #pragma unroll
        for (int k = 0; k < KW; k++) {
            float2 wv = __ldg(&g_wconv2[k * NF + lane]);  // coalesced LDG.64
            wk[k] = pack2(wv.x, wv.y);
        }
        #pragma unroll 2
        for (int u = 0; u < 8; u++) {
            const int tp = tl + 2 * u;
            u64 a0 = 0ull, a1 = 0ull;
            #pragma unroll
            for (int m = 0; m < 16; m++) {
                float4 F = *(const float4*)&s_cum2[tp + 2 * m];
                u64 flo = pack2(F.x, F.y);
                u64 fhi = pack2(F.z, F.w);
                fma2(a0, wk[2 * m], flo);
                if (2 * m + 1 < KW) fma2(a0, wk[2 * m + 1], fhi);
                if (m > 0) fma2(a1, wk[2 * m - 1], flo);
                fma2(a1, wk[2 * m], fhi);
            }
            float l0, h0, l1, h1;
            unpack2(a0, l0, h0);
            unpack2(a1, l1, h1);
            float v0 = l0 + h0, v1 = l1 + h1;
            ov.locd[lane][tp]     = pack2(v0, v0);
            ov.locd[lane][tp + 1] = pack2(v1, v1);
        }
    }

    // W_loc tile: straight coalesced copy of pre-transposed global
    {
        const float4* __restrict__ src = (const float4*)g_wlocT;
        float4* dst = (float4*)s_wloc;
        #pragma unroll
        for (int j = 0; j < 8; j++) dst[tid + j * 128] = src[tid + j * 128];
    }
    __syncthreads();

    // ---- stage 2: two passes of 8 t, register-blocked ----
    const float4 q4 = *((const float4*)(g_q + b * ATT) + lane);
    const float4 we4 = ((const float4*)WE)[lane];
    const u64 q01 = pack2(q4.x, q4.y);
    const u64 q23 = pack2(q4.z, q4.w);
    const float4* __restrict__ MA4 = (const float4*)MA;

    float psum = 0.f;
    #pragma unroll
    for (int p = 0; p < 2; p++) {
        const int ts = tl + p * 8;

        int mv = 0;
        if (lane < 8) mv = MASK[b * T + t0 + ts + lane];
        const unsigned mb = __ballot_sync(0xffffffffu, mv != 0) & 0xffu;

        u64 v01[8], v23[8];
        #pragma unroll
        for (int j = 0; j < 8; j++) {
            if (!((mb >> j) & 1u)) {
                const int t = t0 + ts + j;
                float4 m = MA4[((size_t)b * T + t) * (ATT / 4) + lane];
                v01[j] = add2(q01, pack2(m.x, m.y));
                v23[j] = add2(q23, pack2(m.z, m.w));
            } else {
                v01[j] = q01; v23[j] = q23;
            }
        }
        #pragma unroll 4
        for (int c = 0; c < NF; c++) {
            float4 wf = ((const float4*)s_wloc[c])[lane];   // LDS.128
            u64 w01 = pack2(wf.x, wf.y);
            u64 w23 = pack2(wf.z, wf.w);
            #pragma unroll
            for (int r = 0; r < 4; r++) {
                ulonglong2 L = *(const ulonglong2*)&ov.locd[c][ts + 2 * r];
                fma2(v01[2 * r],     L.x, w01);
                fma2(v23[2 * r],     L.x, w23);
                fma2(v01[2 * r + 1], L.y, w01);
                fma2(v23[2 * r + 1], L.y, w23);
            }
        }

        float myw = 0.f;
        #pragma unroll
        for (int j = 0; j < 8; j++) {
            if (!((mb >> j) & 1u)) {
                float a0, a1, a2, a3;
                unpack2(v01[j], a0, a1);
                unpack2(v23[j], a2, a3);
                float e = we4.x * tanh_apx(a0) + we4.y * tanh_apx(a1)
                        + we4.z * tanh_apx(a2) + we4.w * tanh_apx(a3);
                #pragma unroll
                for (int s = 16; s; s >>= 1)
                    e += __shfl_xor_sync(0xffffffffu, e, s);
                float wexp = __expf(e);   // |e| small: no max subtraction
                if (lane == j) myw = wexp;
                psum += wexp;
            }
        }
        if (lane < 8) {
            WOUT[b * T + t0 + ts + lane] = myw;  // unnormalized; masked -> 0
            s_w[ts + lane] = myw;
        }
    }
    if (lane == 0) atomicAdd(&g_sum[b], psum);

    // all warps done reading ov.locd before we overlay ov.ctx
    __syncthreads();

    // ---- fused context accumulation: warp covers its own 16 t rows ----
    const float4* __restrict__ M4 = (const float4*)MEM + ((size_t)b * T + t0) * (EMB / 4);
    float4 acc0 = make_float4(0.f, 0.f, 0.f, 0.f);
    float4 acc1 = acc0, acc2 = acc0, acc3 = acc0;
    #pragma unroll 4
    for (int j = 0; j < 16; j++) {
        float wt = s_w[tl + j];
        if (wt != 0.f) {   // warp-uniform skip of masked rows
            const float4* row = M4 + (size_t)(tl + j) * (EMB / 4);
            float4 m0 = __ldcs(row + 0 * 32 + lane);
            float4 m1 = __ldcs(row + 1 * 32 + lane);
            float4 m2 = __ldcs(row + 2 * 32 + lane);
            float4 m3 = __ldcs(row + 3 * 32 + lane);
            acc0.x += wt * m0.x; acc0.y += wt * m0.y; acc0.z += wt * m0.z; acc0.w += wt * m0.w;
            acc1.x += wt * m1.x; acc1.y += wt * m1.y; acc1.z += wt * m1.z; acc1.w += wt * m1.w;
            acc2.x += wt * m2.x; acc2.y += wt * m2.y; acc2.z += wt * m2.z; acc2.w += wt * m2.w;
            acc3.x += wt * m3.x; acc3.y += wt * m3.y; acc3.z += wt * m3.z; acc3.w += wt * m3.w;
        }
    }
    ov.ctx[w * 128 + 0 * 32 + lane] = acc0;
    ov.ctx[w * 128 + 1 * 32 + lane] = acc1;
    ov.ctx[w * 128 + 2 * 32 + lane] = acc2;
    ov.ctx[w * 128 + 3 * 32 + lane] = acc3;
    __syncthreads();

    // cross-warp reduce + store per-segment partial (coalesced)
    float4 r0 = ov.ctx[tid];
    float4 r1 = ov.ctx[128 + tid];
    float4 r2 = ov.ctx[256 + tid];
    float4 r3 = ov.ctx[384 + tid];
    float4 r = make_float4(r0.x + r1.x + r2.x + r3.x,
                           r0.y + r1.y + r2.y + r3.y,
                           r0.z + r1.z + r2.z + r3.z,
                           r0.w + r1.w + r2.w + r3.w);
    g_ctxp[(seg * B + b) * 128 + tid] = r;
}

// ---------------------------------------------------------------------------
// Kernel 3: normalize weights + reduce ctx partials. grid (B), 256 thr.
// ---------------------------------------------------------------------------
__global__ void __launch_bounds__(256)
normalize_kernel(float* __restrict__ WROW, float* __restrict__ CTX) {
    const int b = blockIdx.x;
    const int tid = threadIdx.x;
    const float inv = 1.f / g_sum[b];

    float4* __restrict__ W4 = (float4*)(WROW + b * T);
    #pragma unroll
    for (int j = 0; j < 2; j++) {
        float4 v = W4[tid + j * 256];
        v.x *= inv; v.y *= inv; v.z *= inv; v.w *= inv;
        W4[tid + j * 256] = v;
    }
    if (tid < 128) {
        float4 r = make_float4(0.f, 0.f, 0.f, 0.f);
        #pragma unroll
        for (int seg = 0; seg < NSEG; seg++) {
            float4 p = g_ctxp[(seg * B + b) * 128 + tid];
            r.x += p.x; r.y += p.y; r.z += p.z; r.w += p.w;
        }
        ((float4*)CTX)[b * 128 + tid] =
            make_float4(r.x * inv, r.y * inv, r.z * inv, r.w * inv);
    }
}

// ---------------------------------------------------------------------------
extern "C" void kernel_launch(void* const* d_in, const int* in_sizes, int n_in,
                              void* d_out, int out_size) {
    const float* hid   = (const float*)d_in[0];
    const float* mem   = (const float*)d_in[1];
    const float* ma    = (const float*)d_in[2];
    const float* cum   = (const float*)d_in[3];
    const int*   mask  = (const int*)d_in[4];
    const float* wdec  = (const float*)d_in[5];
    const float* wconv = (const float*)d_in[6];
    const float* wloc  = (const float*)d_in[7];
    const float* we    = (const float*)d_in[8];

    float* out_ctx = (float*)d_out;
    float* out_w   = (float*)d_out + B * EMB;

    dim3 gp(B, 16);
    prep_kernel<<<gp, 256>>>(hid, wdec, wloc, wconv);

    cudaLaunchConfig_t cfg = {};
    cfg.gridDim = dim3(NSEG, B);
    cfg.blockDim = dim3(128);
    cfg.dynamicSmemBytes = 0;
    cfg.stream = 0;
    cudaLaunchAttribute attrs[1];
    attrs[0].id = cudaLaunchAttributeProgrammaticStreamSerialization;
    attrs[0].val.programmaticStreamSerializationAllowed = 1;
    cfg.attrs = attrs;
    cfg.numAttrs = 1;
    cudaLaunchKernelEx(&cfg, fused_kernel, mem, ma, cum, mask, we, out_w);

    normalize_kernel<<<B, 256>>>(out_w, out_ctx);
}